// round 3
// baseline (speedup 1.0000x reference)
#include <cuda_runtime.h>

// Inverse 2D DWT, separable L=2 synthesis filters, stride-2 transposed conv,
// padding = L-2 = 0. Collapses to a per-pixel 2x2 butterfly:
//   A_di = ll*g0c[di] + lh*g1c[di]   (column synthesis of (low, LH))
//   B_di = hl*g0c[di] + hh*g1c[di]   (column synthesis of (HL, HH))
//   out[2i+di][2j+dj] = A_di*g0r[dj] + B_di*g1r[dj]
//
// Inputs (metadata order): low [NC,H,W], highs [NC,3,H,W], g0_col[2],
// g1_col[2], g0_row[2], g1_row[2]. Output [NC,2H,2W] float32.

__global__ void __launch_bounds__(256)
idwt2_l2_kernel(const float* __restrict__ low,
                const float* __restrict__ highs,
                const float* __restrict__ g0c_p,
                const float* __restrict__ g1c_p,
                const float* __restrict__ g0r_p,
                const float* __restrict__ g1r_p,
                float* __restrict__ out,
                int NC, int H, int W)
{
    // Uniform filter taps (broadcast loads, L1-resident after first warp).
    const float a0 = __ldg(&g0c_p[0]), a1 = __ldg(&g0c_p[1]);
    const float b0 = __ldg(&g1c_p[0]), b1 = __ldg(&g1c_p[1]);
    const float c0 = __ldg(&g0r_p[0]), c1 = __ldg(&g0r_p[1]);
    const float d0 = __ldg(&g1r_p[0]), d1 = __ldg(&g1r_p[1]);

    const int W2 = W >> 1;                         // input float2 columns
    const long long total = (long long)NC * H * W2;
    long long idx = (long long)blockIdx.x * blockDim.x + threadIdx.x;
    if (idx >= total) return;

    const int j2 = (int)(idx % W2);
    const long long t = idx / W2;
    const int i  = (int)(t % H);
    const int nc = (int)(t / H);

    const long long plane = (long long)H * W;
    const long long rowoff = (long long)i * W + (long long)j2 * 2;

    const float2 ll2 = *reinterpret_cast<const float2*>(low + (long long)nc * plane + rowoff);
    const long long hbase = (long long)nc * 3 * plane + rowoff;
    const float2 lh2 = *reinterpret_cast<const float2*>(highs + hbase);
    const float2 hl2 = *reinterpret_cast<const float2*>(highs + hbase + plane);
    const float2 hh2 = *reinterpret_cast<const float2*>(highs + hbase + 2 * plane);

    float4 r0, r1;
    // input column j = 2*j2
    {
        const float A0 = ll2.x * a0 + lh2.x * b0;
        const float B0 = hl2.x * a0 + hh2.x * b0;
        const float A1 = ll2.x * a1 + lh2.x * b1;
        const float B1 = hl2.x * a1 + hh2.x * b1;
        r0.x = A0 * c0 + B0 * d0;  r0.y = A0 * c1 + B0 * d1;
        r1.x = A1 * c0 + B1 * d0;  r1.y = A1 * c1 + B1 * d1;
    }
    // input column j = 2*j2 + 1
    {
        const float A0 = ll2.y * a0 + lh2.y * b0;
        const float B0 = hl2.y * a0 + hh2.y * b0;
        const float A1 = ll2.y * a1 + lh2.y * b1;
        const float B1 = hl2.y * a1 + hh2.y * b1;
        r0.z = A0 * c0 + B0 * d0;  r0.w = A0 * c1 + B0 * d1;
        r1.z = A1 * c0 + B1 * d0;  r1.w = A1 * c1 + B1 * d1;
    }

    const int Wo = 2 * W;
    const long long ooff = (long long)nc * 4 * plane
                         + (long long)(2 * i) * Wo
                         + (long long)j2 * 4;
    *reinterpret_cast<float4*>(out + ooff)      = r0;   // row 2i
    *reinterpret_cast<float4*>(out + ooff + Wo) = r1;   // row 2i+1
}

extern "C" void kernel_launch(void* const* d_in, const int* in_sizes, int n_in,
                              void* d_out, int out_size)
{
    const float* low   = (const float*)d_in[0];
    const float* highs = (const float*)d_in[1];
    const float* g0c   = (const float*)d_in[2];
    const float* g1c   = (const float*)d_in[3];
    const float* g0r   = (const float*)d_in[4];
    const float* g1r   = (const float*)d_in[5];
    float* out = (float*)d_out;

    // Geometry: H = W = 256 per the problem; NC derived from input size so
    // batch/channel variants still work.
    const int H = 256, W = 256;
    const int NC = in_sizes[0] / (H * W);

    const long long total = (long long)NC * H * (W / 2);
    const int threads = 256;
    const int blocks = (int)((total + threads - 1) / threads);

    idwt2_l2_kernel<<<blocks, threads>>>(low, highs, g0c, g1c, g0r, g1r,
                                         out, NC, H, W);
}

// round 6
// speedup vs baseline: 1.0004x; 1.0004x over previous
#include <cuda_runtime.h>

// Inverse 2D DWT, L=2 separable synthesis, stride 2, padding 0:
// per input pixel, a 2x2 butterfly into the output.
//
// Each thread: 2 input rows x 2 input cols, all 4 planes
//   -> 8x float2 loads (MLP=8), 4x float4 stores (lane-contiguous).
// Streaming hints (__ldcs/__stcs): zero data reuse.

__global__ void __launch_bounds__(256)
idwt2_l2_kernel(const float* __restrict__ low,
                const float* __restrict__ highs,
                const float* __restrict__ g0c_p,
                const float* __restrict__ g1c_p,
                const float* __restrict__ g0r_p,
                const float* __restrict__ g1r_p,
                float* __restrict__ out,
                int NC, int H, int W)
{
    // Uniform filter taps.
    const float a0 = __ldg(&g0c_p[0]), a1 = __ldg(&g0c_p[1]);
    const float b0 = __ldg(&g1c_p[0]), b1 = __ldg(&g1c_p[1]);
    const float c0 = __ldg(&g0r_p[0]), c1 = __ldg(&g0r_p[1]);
    const float d0 = __ldg(&g1r_p[0]), d1 = __ldg(&g1r_p[1]);

    const int W2 = W >> 1;           // float2 columns per input row
    const int H2 = H >> 1;           // row pairs per plane
    const long long total = (long long)NC * H2 * W2;
    const long long idx = (long long)blockIdx.x * blockDim.x + threadIdx.x;
    if (idx >= total) return;

    const int j2 = (int)(idx % W2);
    const long long t = idx / W2;
    const int ri = (int)(t % H2);
    const int nc = (int)(t / H2);
    const int i0 = 2 * ri;           // first of the two input rows

    const long long plane = (long long)H * W;
    const long long off0 = (long long)nc * plane + (long long)i0 * W + (long long)j2 * 2;
    const long long hb   = (long long)nc * 3 * plane + (long long)i0 * W + (long long)j2 * 2;

    // 8 independent streaming loads (two rows x four planes).
    const float2 ll_r0 = __ldcs((const float2*)(low   + off0));
    const float2 ll_r1 = __ldcs((const float2*)(low   + off0 + W));
    const float2 lh_r0 = __ldcs((const float2*)(highs + hb));
    const float2 lh_r1 = __ldcs((const float2*)(highs + hb + W));
    const float2 hl_r0 = __ldcs((const float2*)(highs + hb + plane));
    const float2 hl_r1 = __ldcs((const float2*)(highs + hb + plane + W));
    const float2 hh_r0 = __ldcs((const float2*)(highs + hb + 2 * plane));
    const float2 hh_r1 = __ldcs((const float2*)(highs + hb + 2 * plane + W));

    const int Wo = 2 * W;
    const long long obase = (long long)nc * 4 * plane
                          + (long long)(2 * i0) * Wo
                          + (long long)j2 * 4;

    // Butterfly for one input row: produces two output rows (float4 each).
    #define BUTTERFLY(LL, LH, HL, HH, OOFF)                                   \
    {                                                                         \
        float4 r0, r1;                                                        \
        {   /* input col j = 2*j2 */                                          \
            const float A0 = (LL).x * a0 + (LH).x * b0;                       \
            const float B0 = (HL).x * a0 + (HH).x * b0;                       \
            const float A1 = (LL).x * a1 + (LH).x * b1;                       \
            const float B1 = (HL).x * a1 + (HH).x * b1;                       \
            r0.x = A0 * c0 + B0 * d0;  r0.y = A0 * c1 + B0 * d1;              \
            r1.x = A1 * c0 + B1 * d0;  r1.y = A1 * c1 + B1 * d1;              \
        }                                                                     \
        {   /* input col j = 2*j2 + 1 */                                      \
            const float A0 = (LL).y * a0 + (LH).y * b0;                       \
            const float B0 = (HL).y * a0 + (HH).y * b0;                       \
            const float A1 = (LL).y * a1 + (LH).y * b1;                       \
            const float B1 = (HL).y * a1 + (HH).y * b1;                       \
            r0.z = A0 * c0 + B0 * d0;  r0.w = A0 * c1 + B0 * d1;              \
            r1.z = A1 * c0 + B1 * d0;  r1.w = A1 * c1 + B1 * d1;              \
        }                                                                     \
        __stcs((float4*)(out + (OOFF)), r0);                                  \
        __stcs((float4*)(out + (OOFF) + Wo), r1);                             \
    }

    BUTTERFLY(ll_r0, lh_r0, hl_r0, hh_r0, obase);            // rows 2i0, 2i0+1
    BUTTERFLY(ll_r1, lh_r1, hl_r1, hh_r1, obase + 2 * Wo);   // rows 2i0+2, 2i0+3

    #undef BUTTERFLY
}

extern "C" void kernel_launch(void* const* d_in, const int* in_sizes, int n_in,
                              void* d_out, int out_size)
{
    const float* low   = (const float*)d_in[0];
    const float* highs = (const float*)d_in[1];
    const float* g0c   = (const float*)d_in[2];
    const float* g1c   = (const float*)d_in[3];
    const float* g0r   = (const float*)d_in[4];
    const float* g1r   = (const float*)d_in[5];
    float* out = (float*)d_out;

    const int H = 256, W = 256;
    const int NC = in_sizes[0] / (H * W);

    const long long total = (long long)NC * (H / 2) * (W / 2);
    const int threads = 256;
    const int blocks = (int)((total + threads - 1) / threads);

    idwt2_l2_kernel<<<blocks, threads>>>(low, highs, g0c, g1c, g0r, g1r,
                                         out, NC, H, W);
}